// round 3
// baseline (speedup 1.0000x reference)
#include <cuda_runtime.h>
#include <math.h>

#define NPTS 65536
#define NS   16
#define CH   128
#define EPSB 1e-5f
#define LOG2E 1.4426950408889634f

typedef unsigned long long ull;

__device__ __forceinline__ ull pack2(float lo, float hi) {
    ull r; asm("mov.b64 %0,{%1,%2};" : "=l"(r) : "f"(lo), "f"(hi)); return r;
}
__device__ __forceinline__ void unpack2(ull v, float& lo, float& hi) {
    asm("mov.b64 {%0,%1},%2;" : "=f"(lo), "=f"(hi) : "l"(v));
}
__device__ __forceinline__ ull ffma2(ull a, ull b, ull c) {
    ull d; asm("fma.rn.f32x2 %0,%1,%2,%3;" : "=l"(d) : "l"(a), "l"(b), "l"(c)); return d;
}
__device__ __forceinline__ ull fmul2(ull a, ull b) {
    ull d; asm("mul.rn.f32x2 %0,%1,%2;" : "=l"(d) : "l"(a), "l"(b)); return d;
}

// static device scratch (allocation-guard safe)
__device__ float  g_q [(size_t)NPTS * CH];
__device__ float  g_kv[(size_t)NPTS * 2 * CH];   // interleaved (k,v) pairs
__device__ float4 g_p4[NPTS];

// ---------------------------------------------------------------------------
// prep: pack positions into float4
// ---------------------------------------------------------------------------
__global__ void prep_kernel(const float* __restrict__ p)
{
    int i = blockIdx.x * 256 + threadIdx.x;
    g_p4[i] = make_float4(p[3 * i + 0], p[3 * i + 1], p[3 * i + 2], 0.f);
}

// ---------------------------------------------------------------------------
// Kernel 1: QKV GEMM. tile 256(m) x 128(n), 256 threads, 16x8 micro-tile,
// f32x2 pairs along m (pack-free via ulonglong2 smem reads).
// grid = (256, 3): blockIdx.y selects q/k/v. K/V stored interleaved in g_kv.
// ---------------------------------------------------------------------------
#define KC 16

__global__ void __launch_bounds__(256)
qkv_kernel(const float* __restrict__ x,
           const float* __restrict__ wq, const float* __restrict__ bq,
           const float* __restrict__ wk, const float* __restrict__ bk,
           const float* __restrict__ wv, const float* __restrict__ bv)
{
    __shared__ float Xs[KC][260];   // [k][m]  (260 floats: 16B-aligned rows)
    __shared__ float Ws[KC][136];   // [k][n]

    const int m0 = blockIdx.x * 256;
    const float* W;
    const float* bias;
    const int sel = blockIdx.y;
    if (sel == 0)      { W = wq; bias = bq; }
    else if (sel == 1) { W = wk; bias = bk; }
    else               { W = wv; bias = bv; }

    const int tid = threadIdx.x;
    const int tx  = tid & 15;    // n: cols tx*8..tx*8+7
    const int ty  = tid >> 4;    // m: rows ty*16..ty*16+15

    ull acc2[8][8];
#pragma unroll
    for (int i = 0; i < 8; ++i)
#pragma unroll
        for (int j = 0; j < 8; ++j) acc2[i][j] = 0ull;

    // global-load assignment:
    //  x: thread -> row m0+tid, 4 float4 over the 16-wide k-chunk
    //  W: thread -> row tid>>1, half (tid&1)*8, 2 float4
    const int wrow = tid >> 1;
    const int wko  = (tid & 1) * 8;

    float4 xp[4], wp_[2];
#pragma unroll
    for (int i = 0; i < 4; ++i)
        xp[i] = *(const float4*)&x[(size_t)(m0 + tid) * 128 + 4 * i];
#pragma unroll
    for (int i = 0; i < 2; ++i)
        wp_[i] = *(const float4*)&W[(size_t)wrow * 128 + wko + 4 * i];

#pragma unroll 1
    for (int c = 0; c < 8; ++c) {
        // stage chunk into smem (transposed)
#pragma unroll
        for (int i = 0; i < 4; ++i) {
            Xs[4 * i + 0][tid] = xp[i].x; Xs[4 * i + 1][tid] = xp[i].y;
            Xs[4 * i + 2][tid] = xp[i].z; Xs[4 * i + 3][tid] = xp[i].w;
        }
#pragma unroll
        for (int i = 0; i < 2; ++i) {
            Ws[wko + 4 * i + 0][wrow] = wp_[i].x; Ws[wko + 4 * i + 1][wrow] = wp_[i].y;
            Ws[wko + 4 * i + 2][wrow] = wp_[i].z; Ws[wko + 4 * i + 3][wrow] = wp_[i].w;
        }
        __syncthreads();

        if (c < 7) {
            int kc = (c + 1) * KC;
#pragma unroll
            for (int i = 0; i < 4; ++i)
                xp[i] = *(const float4*)&x[(size_t)(m0 + tid) * 128 + kc + 4 * i];
#pragma unroll
            for (int i = 0; i < 2; ++i)
                wp_[i] = *(const float4*)&W[(size_t)wrow * 128 + kc + wko + 4 * i];
        }

#pragma unroll
        for (int k = 0; k < KC; ++k) {
            // a: 16 m-floats = 8 f32x2 pairs, loaded pack-free
            ull a2[8];
#pragma unroll
            for (int i = 0; i < 4; ++i) {
                ulonglong2 q = *(const ulonglong2*)&Xs[k][ty * 16 + 4 * i];
                a2[2 * i] = q.x; a2[2 * i + 1] = q.y;
            }
            float4 b0 = *(const float4*)&Ws[k][tx * 8];
            float4 b1 = *(const float4*)&Ws[k][tx * 8 + 4];
            ull bb[8];
            bb[0] = pack2(b0.x, b0.x); bb[1] = pack2(b0.y, b0.y);
            bb[2] = pack2(b0.z, b0.z); bb[3] = pack2(b0.w, b0.w);
            bb[4] = pack2(b1.x, b1.x); bb[5] = pack2(b1.y, b1.y);
            bb[6] = pack2(b1.z, b1.z); bb[7] = pack2(b1.w, b1.w);
#pragma unroll
            for (int i = 0; i < 8; ++i)
#pragma unroll
                for (int j = 0; j < 8; ++j)
                    acc2[i][j] = ffma2(a2[i], bb[j], acc2[i][j]);
        }
        __syncthreads();
    }

    // epilogue: bias + store
    float bs[8];
    {
        float4 t0 = *(const float4*)&bias[tx * 8];
        float4 t1 = *(const float4*)&bias[tx * 8 + 4];
        bs[0] = t0.x; bs[1] = t0.y; bs[2] = t0.z; bs[3] = t0.w;
        bs[4] = t1.x; bs[5] = t1.y; bs[6] = t1.z; bs[7] = t1.w;
    }
#pragma unroll
    for (int mi = 0; mi < 8; ++mi) {
        float lo[8], hi[8];
#pragma unroll
        for (int j = 0; j < 8; ++j) {
            unpack2(acc2[mi][j], lo[j], hi[j]);
            lo[j] += bs[j]; hi[j] += bs[j];
        }
        const int mlo = m0 + ty * 16 + 2 * mi;
        if (sel == 0) {
            size_t b0 = (size_t)mlo * 128 + tx * 8;
            *(float4*)&g_q[b0]       = make_float4(lo[0], lo[1], lo[2], lo[3]);
            *(float4*)&g_q[b0 + 4]   = make_float4(lo[4], lo[5], lo[6], lo[7]);
            *(float4*)&g_q[b0 + 128] = make_float4(hi[0], hi[1], hi[2], hi[3]);
            *(float4*)&g_q[b0 + 132] = make_float4(hi[4], hi[5], hi[6], hi[7]);
        } else {
            const int off = (sel == 1) ? 0 : 1;
            size_t b0 = (size_t)mlo * 256 + 2 * (tx * 8) + off;
#pragma unroll
            for (int j = 0; j < 8; ++j) {
                g_kv[b0 + 2 * j]       = lo[j];
                g_kv[b0 + 256 + 2 * j] = hi[j];
            }
        }
    }
}

// ---------------------------------------------------------------------------
// Kernel 2: per-point neighborhood attention.
// Lane owns channels lane+32r; softmax column o = lane&15 is lane-local.
// GEMV1: f32x2 partials + XOR reduce-scatter.  GEMV2: half-warp split.
// Base-2 softmax (log2e folded into w2 weights).
// ---------------------------------------------------------------------------
#define PPW 8

__global__ void __launch_bounds__(128, 3)
attn_kernel(const int* __restrict__ idx,
            const float* __restrict__ pw1, const float* __restrict__ pb1,
            const float* __restrict__ pbng, const float* __restrict__ pbnb,
            const float* __restrict__ pbnm, const float* __restrict__ pbnv,
            const float* __restrict__ pw2, const float* __restrict__ pb2,
            const float* __restrict__ bn1g, const float* __restrict__ bn1b,
            const float* __restrict__ bn1m, const float* __restrict__ bn1v,
            const float* __restrict__ ww1, const float* __restrict__ wb1,
            const float* __restrict__ bn2g, const float* __restrict__ bn2b,
            const float* __restrict__ bn2m, const float* __restrict__ bn2v,
            const float* __restrict__ ww2, const float* __restrict__ wb2,
            float* __restrict__ out)
{
    const int lane = threadIdx.x & 31;
    const int gw   = blockIdx.x * (blockDim.x >> 5) + (threadIdx.x >> 5);
    const int o    = lane & 15;
    const int u0   = (lane & 16) ? 8 : 0;   // GEMV2 half-split range

    // GEMV1 weights, XOR-permuted, f32x2-packed (64 regs)
    ull w1c2[8][4];
#pragma unroll
    for (int j = 0; j < 8; ++j)
#pragma unroll
        for (int r = 0; r < 4; ++r) {
            int c = lane + 32 * r;
            w1c2[j][r] = pack2(ww1[(o ^ (2 * j)) * CH + c],
                               ww1[(o ^ (2 * j + 1)) * CH + c]);
        }

    // GEMV2 half-row, log2e folded
    float w2r8[8];
#pragma unroll
    for (int u = 0; u < 8; ++u) w2r8[u] = ww2[o * 16 + u0 + u] * LOG2E;
    const float b2u = wb2[o] * LOG2E;

    const float s2    = bn2g[o] * rsqrtf(bn2v[o] + EPSB);
    const float b2fld = bn2b[o] - bn2m[o] * s2 + wb1[o] * s2;  // fold w1 bias

    float s1[4], b1f[4], pw2v[4][3], pb2v[4];
#pragma unroll
    for (int r = 0; r < 4; ++r) {
        int c = lane + 32 * r;
        float s = bn1g[c] * rsqrtf(bn1v[c] + EPSB);
        s1[r]  = s;
        b1f[r] = bn1b[c] - bn1m[c] * s;
        pw2v[r][0] = pw2[c * 3 + 0];
        pw2v[r][1] = pw2[c * 3 + 1];
        pw2v[r][2] = pw2[c * 3 + 2];
        pb2v[r] = pb2[c];
    }
    // linear_p stage 1 with BN folded: tt = relu(Af*pr + df)
    float Af[9], df[3];
#pragma unroll
    for (int a = 0; a < 3; ++a) {
        float s  = pbng[a] * rsqrtf(pbnv[a] + EPSB);
        float sh = pbnb[a] - pbnm[a] * s;
#pragma unroll
        for (int b = 0; b < 3; ++b) Af[a * 3 + b] = s * pw1[a * 3 + b];
        df[a] = s * pb1[a] + sh;
    }

    const float2* kvp = (const float2*)g_kv;

#pragma unroll 1
    for (int t = 0; t < PPW; ++t) {
        const int i = gw * PPW + t;

        const float4 pi = g_p4[i];
        float xqf[4];
#pragma unroll
        for (int r = 0; r < 4; ++r) {
            float xq = g_q[(size_t)i * CH + lane + 32 * r];
            xqf[r] = b1f[r] - s1[r] * xq;
        }
        const int myj = idx[i * NS + o];

        float mrun = -INFINITY, Z = 0.f;
        float A[4] = {0.f, 0.f, 0.f, 0.f};

        // prefetch neighbor 0
        int jA = __shfl_sync(0xffffffffu, myj, 0);
        float2 kvA[4];
#pragma unroll
        for (int r = 0; r < 4; ++r)
            kvA[r] = kvp[(size_t)jA * CH + lane + 32 * r];
        float4 pjA = g_p4[jA];

#pragma unroll 2
        for (int n = 0; n < NS; ++n) {
            float2 kv[4];
#pragma unroll
            for (int r = 0; r < 4; ++r) kv[r] = kvA[r];
            float pr0 = pjA.x - pi.x, pr1 = pjA.y - pi.y, pr2 = pjA.z - pi.z;

            if (n < NS - 1) {
                int jn = __shfl_sync(0xffffffffu, myj, n + 1);
#pragma unroll
                for (int r = 0; r < 4; ++r)
                    kvA[r] = kvp[(size_t)jn * CH + lane + 32 * r];
                pjA = g_p4[jn];
            }

            // linear_p stage 1 (BN folded)
            float tt[3];
#pragma unroll
            for (int a = 0; a < 3; ++a) {
                float v = fmaf(pr2, Af[a * 3 + 2],
                          fmaf(pr1, Af[a * 3 + 1],
                          fmaf(pr0, Af[a * 3 + 0], df[a])));
                tt[a] = fmaxf(v, 0.f);
            }
            // linear_p stage 2 + w-pre
            float pe[4], wp[4];
#pragma unroll
            for (int r = 0; r < 4; ++r) {
                pe[r] = fmaf(tt[2], pw2v[r][2],
                        fmaf(tt[1], pw2v[r][1],
                        fmaf(tt[0], pw2v[r][0], pb2v[r])));
                wp[r] = fmaxf(fmaf(kv[r].x + pe[r], s1[r], xqf[r]), 0.f);
            }

            // GEMV1 partials (f32x2, XOR-permuted)
            ull wp2[4];
#pragma unroll
            for (int r = 0; r < 4; ++r) wp2[r] = pack2(wp[r], wp[r]);
            ull acc2[8];
#pragma unroll
            for (int j = 0; j < 8; ++j) {
                acc2[j] = fmul2(wp2[0], w1c2[j][0]);
                acc2[j] = ffma2(wp2[1], w1c2[j][1], acc2[j]);
                acc2[j] = ffma2(wp2[2], w1c2[j][2], acc2[j]);
                acc2[j] = ffma2(wp2[3], w1c2[j][3], acc2[j]);
            }
            float a[16];
#pragma unroll
            for (int j = 0; j < 8; ++j) unpack2(acc2[j], a[2 * j], a[2 * j + 1]);

            // XOR reduce-scatter
#pragma unroll
            for (int k = 0; k < 8; ++k) a[k] += __shfl_xor_sync(0xffffffffu, a[k + 8], 8);
#pragma unroll
            for (int k = 0; k < 4; ++k) a[k] += __shfl_xor_sync(0xffffffffu, a[k + 4], 4);
#pragma unroll
            for (int k = 0; k < 2; ++k) a[k] += __shfl_xor_sync(0xffffffffu, a[k + 2], 2);
            a[0] += __shfl_xor_sync(0xffffffffu, a[1], 1);
            float w1s = a[0] + __shfl_xor_sync(0xffffffffu, a[0], 16);

            // BN2 + ReLU
            float tv = fmaxf(fmaf(w1s, s2, b2fld), 0.f);

            // GEMV2 half-warp split: 8 shfl + 8 fma + exchange
            float part = __shfl_sync(0xffffffffu, tv, u0) * w2r8[0];
#pragma unroll
            for (int u = 1; u < 8; ++u)
                part = fmaf(__shfl_sync(0xffffffffu, tv, u0 + u), w2r8[u], part);
            float w2v = part + __shfl_xor_sync(0xffffffffu, part, 16) + b2u;

            // online softmax, base 2 (log2e already folded into logits)
            float nm   = fmaxf(mrun, w2v);
            float corr = exp2f(mrun - nm);
            float e    = exp2f(w2v - nm);
            Z = fmaf(Z, corr, e);
#pragma unroll
            for (int r = 0; r < 4; ++r)
                A[r] = fmaf(A[r], corr, (kv[r].y + pe[r]) * e);
            mrun = nm;
        }

        const float inv = __frcp_rn(Z);
#pragma unroll
        for (int r = 0; r < 4; ++r)
            out[(size_t)i * CH + lane + 32 * r] = A[r] * inv;
    }
}

// ---------------------------------------------------------------------------
extern "C" void kernel_launch(void* const* d_in, const int* in_sizes, int n_in,
                              void* d_out, int out_size)
{
    const float* p    = (const float*)d_in[0];
    const float* x    = (const float*)d_in[1];
    const int*   idx  = (const int*)  d_in[2];
    const float* wq   = (const float*)d_in[3];
    const float* bq   = (const float*)d_in[4];
    const float* wk   = (const float*)d_in[5];
    const float* bk   = (const float*)d_in[6];
    const float* wv   = (const float*)d_in[7];
    const float* bv   = (const float*)d_in[8];
    const float* pw1  = (const float*)d_in[9];
    const float* pb1  = (const float*)d_in[10];
    const float* pbng = (const float*)d_in[11];
    const float* pbnb = (const float*)d_in[12];
    const float* pbnm = (const float*)d_in[13];
    const float* pbnv = (const float*)d_in[14];
    const float* pw2  = (const float*)d_in[15];
    const float* pb2  = (const float*)d_in[16];
    const float* bn1g = (const float*)d_in[17];
    const float* bn1b = (const float*)d_in[18];
    const float* bn1m = (const float*)d_in[19];
    const float* bn1v = (const float*)d_in[20];
    const float* ww1  = (const float*)d_in[21];
    const float* wb1  = (const float*)d_in[22];
    const float* bn2g = (const float*)d_in[23];
    const float* bn2b = (const float*)d_in[24];
    const float* bn2m = (const float*)d_in[25];
    const float* bn2v = (const float*)d_in[26];
    const float* ww2  = (const float*)d_in[27];
    const float* wb2  = (const float*)d_in[28];
    float* out = (float*)d_out;

    prep_kernel<<<NPTS / 256, 256>>>(p);
    qkv_kernel<<<dim3(NPTS / 256, 3), 256>>>(x, wq, bq, wk, bk, wv, bv);

    attn_kernel<<<NPTS / (PPW * 4), 128>>>(
        idx,
        pw1, pb1, pbng, pbnb, pbnm, pbnv, pw2, pb2,
        bn1g, bn1b, bn1m, bn1v, ww1, wb1,
        bn2g, bn2b, bn2m, bn2v, ww2, wb2,
        out);
}